// round 15
// baseline (speedup 1.0000x reference)
#include <cuda_runtime.h>

#define NPR     16384            // values per row
#define NBINS   100
#define THREADS 256
#define NSUB    (THREADS / 16)   // 16 half-warp sub-histograms
#define HSTRIDE 104              // padded stride (104 % 32 == 8 -> bank shift between regions)
#define F4_PER_THREAD (NPR / (4 * THREADS))  // 16
#define BATCH   8                // float4 per staged batch

// FINAL (R14): best measured configuration. Three identical-source benches:
// 43.52 / 44.54 / 45.12 us at 6297-6365 GB/s — the documented LTS chip-cap
// run-to-run band. 256 MB mandatory single-pass read at ~6.3 TB/s = 40.6 us
// floor; kernel is ~94-98% pure transfer at that ceiling. All structural
// alternatives (MLP staging, persistent grid, prefetch pipeline, atomic-free
// counters) measured and bounded in R3-R11; none beat this.
__global__ __launch_bounds__(THREADS)
void hist_rows_kernel(const float* __restrict__ x, float* __restrict__ out)
{
    __shared__ int hist[NSUB * HSTRIDE];

    const int tid = threadIdx.x;

    #pragma unroll
    for (int i = tid; i < NSUB * HSTRIDE; i += THREADS)
        hist[i] = 0;
    __syncthreads();

    // Half-warp-private histogram region: lanes 0-15 / 16-31 of each warp
    // use separate sub-histograms -> ~2x fewer same-address ATOMS collisions.
    int* h = &hist[(tid >> 4) * HSTRIDE];

    const float4* row =
        reinterpret_cast<const float4*>(x) + (size_t)blockIdx.x * (NPR / 4);

    #pragma unroll
    for (int outer = 0; outer < F4_PER_THREAD / BATCH; outer++) {
        // Stage a batch of independent LDG.128 (streaming: data read once)
        float4 v[BATCH];
        #pragma unroll
        for (int j = 0; j < BATCH; j++)
            v[j] = __ldcs(&row[(outer * BATCH + j) * THREADS + tid]);

        // Drain into shared atomics (no-return ATOMS: RMW in the LSU pipe,
        // no scoreboard round-trip).
        // Exact ref semantics: trunc->int, then floor(100*xi/256) == (xi*100)>>8
        // (100*xi < 2^16 exactly representable; /256 is a power of two).
        #pragma unroll
        for (int j = 0; j < BATCH; j++) {
            atomicAdd(&h[((int)v[j].x * NBINS) >> 8], 1);
            atomicAdd(&h[((int)v[j].y * NBINS) >> 8], 1);
            atomicAdd(&h[((int)v[j].z * NBINS) >> 8], 1);
            atomicAdd(&h[((int)v[j].w * NBINS) >> 8], 1);
        }
    }
    __syncthreads();

    // Reduce 16 sub-histograms and emit float counts
    for (int b = tid; b < NBINS; b += THREADS) {
        int s = 0;
        #pragma unroll
        for (int w = 0; w < NSUB; w++)
            s += hist[w * HSTRIDE + b];
        out[(size_t)blockIdx.x * NBINS + b] = (float)s;
    }
}

extern "C" void kernel_launch(void* const* d_in, const int* in_sizes, int n_in,
                              void* d_out, int out_size)
{
    const float* x = (const float*)d_in[0];
    float* out = (float*)d_out;
    const int rows = out_size / NBINS;   // 4096
    hist_rows_kernel<<<rows, THREADS>>>(x, out);
}

// round 16
// speedup vs baseline: 1.0319x; 1.0319x over previous
#include <cuda_runtime.h>

#define NPR     16384            // values per row
#define NBINS   100
#define THREADS 256
#define NSUB    (THREADS / 16)   // 16 half-warp sub-histograms
#define HSTRIDE 104              // padded stride (104 % 32 == 8 -> bank shift between regions)
#define F4_PER_THREAD (NPR / (4 * THREADS))  // 16
#define BATCH   8                // float4 per staged batch

// FINAL (R15): plateau-verified winner. Four identical-source benches:
// 43.52 / 44.54 / 45.12 / 45.57 us at 6190-6365 GB/s — the documented
// path-independent LTS chip-cap band (~6300 B/cyc full-chip). 256 MB
// mandatory single-pass read at the achieved rate = 40.2-41.3 us floor;
// kernel overhead above mandatory traffic is a stable ~6%. All structural
// alternatives measured and bounded (R3-R11): MLP staging 8/16, occupancy
// 21-94%, persistent grid, prefetch pipelines — tied; atomic-free
// lane-private counters — 2.4x worse. No remaining lever exceeds the
// run-to-run noise band.
__global__ __launch_bounds__(THREADS)
void hist_rows_kernel(const float* __restrict__ x, float* __restrict__ out)
{
    __shared__ int hist[NSUB * HSTRIDE];

    const int tid = threadIdx.x;

    #pragma unroll
    for (int i = tid; i < NSUB * HSTRIDE; i += THREADS)
        hist[i] = 0;
    __syncthreads();

    // Half-warp-private histogram region: lanes 0-15 / 16-31 of each warp
    // use separate sub-histograms -> ~2x fewer same-address ATOMS collisions.
    int* h = &hist[(tid >> 4) * HSTRIDE];

    const float4* row =
        reinterpret_cast<const float4*>(x) + (size_t)blockIdx.x * (NPR / 4);

    #pragma unroll
    for (int outer = 0; outer < F4_PER_THREAD / BATCH; outer++) {
        // Stage a batch of independent LDG.128 (streaming: data read once)
        float4 v[BATCH];
        #pragma unroll
        for (int j = 0; j < BATCH; j++)
            v[j] = __ldcs(&row[(outer * BATCH + j) * THREADS + tid]);

        // Drain into shared atomics (no-return ATOMS: RMW in the LSU pipe,
        // no scoreboard round-trip).
        // Exact ref semantics: trunc->int, then floor(100*xi/256) == (xi*100)>>8
        // (100*xi < 2^16 exactly representable; /256 is a power of two).
        #pragma unroll
        for (int j = 0; j < BATCH; j++) {
            atomicAdd(&h[((int)v[j].x * NBINS) >> 8], 1);
            atomicAdd(&h[((int)v[j].y * NBINS) >> 8], 1);
            atomicAdd(&h[((int)v[j].z * NBINS) >> 8], 1);
            atomicAdd(&h[((int)v[j].w * NBINS) >> 8], 1);
        }
    }
    __syncthreads();

    // Reduce 16 sub-histograms and emit float counts
    for (int b = tid; b < NBINS; b += THREADS) {
        int s = 0;
        #pragma unroll
        for (int w = 0; w < NSUB; w++)
            s += hist[w * HSTRIDE + b];
        out[(size_t)blockIdx.x * NBINS + b] = (float)s;
    }
}

extern "C" void kernel_launch(void* const* d_in, const int* in_sizes, int n_in,
                              void* d_out, int out_size)
{
    const float* x = (const float*)d_in[0];
    float* out = (float*)d_out;
    const int rows = out_size / NBINS;   // 4096
    hist_rows_kernel<<<rows, THREADS>>>(x, out);
}

// round 17
// speedup vs baseline: 1.0387x; 1.0066x over previous
#include <cuda_runtime.h>

#define NPR     16384            // values per row
#define NBINS   100
#define THREADS 256
#define NSUB    (THREADS / 16)   // 16 half-warp sub-histograms
#define HSTRIDE 104              // padded stride (104 % 32 == 8 -> bank shift between regions)
#define F4_PER_THREAD (NPR / (4 * THREADS))  // 16
#define BATCH   8                // float4 per staged batch

// FINAL (R16): plateau-verified winner, five identical-source benches:
// 43.52 / 44.16 / 44.54 / 45.12 / 45.57 us at 6190-6365 GB/s — the
// documented path-independent LTS chip-cap band (~6300 B/cyc full-chip).
// 256 MB mandatory single-pass read; kernel time is ~6% above each run's
// pure-transfer floor, with that residual shown immovable (persistent grid,
// prefetch pipelines, occupancy/MLP sweeps all tied; atomic-free counters
// 2.4x worse). No remaining lever's predicted upside exceeds the ±1 us
// run-to-run noise band.
__global__ __launch_bounds__(THREADS)
void hist_rows_kernel(const float* __restrict__ x, float* __restrict__ out)
{
    __shared__ int hist[NSUB * HSTRIDE];

    const int tid = threadIdx.x;

    #pragma unroll
    for (int i = tid; i < NSUB * HSTRIDE; i += THREADS)
        hist[i] = 0;
    __syncthreads();

    // Half-warp-private histogram region: lanes 0-15 / 16-31 of each warp
    // use separate sub-histograms -> ~2x fewer same-address ATOMS collisions.
    int* h = &hist[(tid >> 4) * HSTRIDE];

    const float4* row =
        reinterpret_cast<const float4*>(x) + (size_t)blockIdx.x * (NPR / 4);

    #pragma unroll
    for (int outer = 0; outer < F4_PER_THREAD / BATCH; outer++) {
        // Stage a batch of independent LDG.128 (streaming: data read once)
        float4 v[BATCH];
        #pragma unroll
        for (int j = 0; j < BATCH; j++)
            v[j] = __ldcs(&row[(outer * BATCH + j) * THREADS + tid]);

        // Drain into shared atomics (no-return ATOMS: RMW in the LSU pipe,
        // no scoreboard round-trip).
        // Exact ref semantics: trunc->int, then floor(100*xi/256) == (xi*100)>>8
        // (100*xi < 2^16 exactly representable; /256 is a power of two).
        #pragma unroll
        for (int j = 0; j < BATCH; j++) {
            atomicAdd(&h[((int)v[j].x * NBINS) >> 8], 1);
            atomicAdd(&h[((int)v[j].y * NBINS) >> 8], 1);
            atomicAdd(&h[((int)v[j].z * NBINS) >> 8], 1);
            atomicAdd(&h[((int)v[j].w * NBINS) >> 8], 1);
        }
    }
    __syncthreads();

    // Reduce 16 sub-histograms and emit float counts
    for (int b = tid; b < NBINS; b += THREADS) {
        int s = 0;
        #pragma unroll
        for (int w = 0; w < NSUB; w++)
            s += hist[w * HSTRIDE + b];
        out[(size_t)blockIdx.x * NBINS + b] = (float)s;
    }
}

extern "C" void kernel_launch(void* const* d_in, const int* in_sizes, int n_in,
                              void* d_out, int out_size)
{
    const float* x = (const float*)d_in[0];
    float* out = (float*)d_out;
    const int rows = out_size / NBINS;   // 4096
    hist_rows_kernel<<<rows, THREADS>>>(x, out);
}